// round 12
// baseline (speedup 1.0000x reference)
#include <cuda_runtime.h>
#include <cuda_fp16.h>
#include <cstdint>
#include <cstddef>

#define B_  256
#define T_  512
#define I_  512
#define H_  1024
#define HB_ 256
#define O_  128
#define M_  (B_ * T_)     // 131072

// ---------------------------------------------------------------------------
// Scratch (device globals; allocation is forbidden)
// ---------------------------------------------------------------------------
__device__ __align__(1024) float g_u[(size_t)T_ * B_ * H_];   // 512 MB
__device__ __align__(1024) float g_acc[B_ * H_];
__device__ __align__(1024) __half g_xh[(size_t)M_ * I_];      // 128 MB each
__device__ __align__(1024) __half g_xm[(size_t)M_ * I_];
__device__ __align__(1024) __half g_wh[H_ * I_];              // 1 MB each, [n][k]
__device__ __align__(1024) __half g_wm[H_ * I_];

// ---------------------------------------------------------------------------
// Split kernels: fp16 two-term split x = h + m  (h=fl16(x), m=fl16(x-h))
// ---------------------------------------------------------------------------
__global__ __launch_bounds__(256)
void split_x_kernel(const float* __restrict__ x) {
    size_t i = (size_t)blockIdx.x * blockDim.x + threadIdx.x;  // float4 index
    float4 v = reinterpret_cast<const float4*>(x)[i];
    float f[4] = {v.x, v.y, v.z, v.w};
    __half h[4], m4[4];
#pragma unroll
    for (int j = 0; j < 4; j++) {
        float a = f[j];
        __half hh = __float2half_rn(a);
        float r = a - __half2float(hh);
        h[j] = hh;
        m4[j] = __float2half_rn(r);
    }
    __half2* ph = reinterpret_cast<__half2*>(g_xh);
    __half2* pm = reinterpret_cast<__half2*>(g_xm);
    ph[2 * i]     = __half2(h[0], h[1]);
    ph[2 * i + 1] = __half2(h[2], h[3]);
    pm[2 * i]     = __half2(m4[0], m4[1]);
    pm[2 * i + 1] = __half2(m4[2], m4[3]);
}

__global__ __launch_bounds__(256)
void split_w_kernel(const float* __restrict__ Wb) {
    int idx = blockIdx.x * 256 + threadIdx.x;   // n*I + k
    int n = idx >> 9;
    int k = idx & (I_ - 1);
    int nb = n >> 8;
    int hb = n & (HB_ - 1);
    float a = Wb[((size_t)nb * I_ + k) * HB_ + hb];
    __half hh = __float2half_rn(a);
    float r = a - __half2float(hh);
    g_wh[idx] = hh;
    g_wm[idx] = __float2half_rn(r);
}

// no-op probe so the GEMM sits at absolute launch index 3 (the ncu capture slot)
__global__ void probe_kernel() {}

// ---------------------------------------------------------------------------
// mma.sync fp16 GEMM, 3 products (hh, hm, mh) — EXACT round-9 winner schedule.
// CTA tile 128x128, warp tile 64x32 (2m x 4n warps), K-chunk 32,
// 3-stage cp.async ring, ONE __syncthreads per chunk, 2 CTAs/SM.
// ---------------------------------------------------------------------------
#define KC 32
#define NCHUNK (I_ / KC)           // 16
#define PART_BYTES (128 * KC * 2)  // 8192 (128 rows x 64B)
#define STAGE_BYTES (4 * PART_BYTES)   // 32768: 2 A parts + 2 B parts
#define SMEM_GEMM (3 * STAGE_BYTES)    // 98304 -> 2 CTAs/SM

__device__ __forceinline__ uint32_t smem_u32(const void* p) {
    uint32_t a;
    asm("{ .reg .u64 t; cvta.to.shared.u64 t, %1; cvt.u32.u64 %0, t; }"
        : "=r"(a) : "l"(p));
    return a;
}
// 64B-row swizzle: row r (0..127), 16B slot h (0..3) — conflict-free per phase
__device__ __forceinline__ uint32_t sw64(int r, int h) {
    return (uint32_t)(r * 64 + ((h ^ ((r >> 1) & 3)) << 4));
}

#define CP16(dst, src) \
    asm volatile("cp.async.cg.shared.global [%0], [%1], 16;" \
                 :: "r"(dst), "l"(src))
#define CPCOMMIT() asm volatile("cp.async.commit_group;" ::: "memory")
#define CPWAIT(n)  asm volatile("cp.async.wait_group %0;" :: "n"(n) : "memory")

#define LDSM4(r0, r1, r2, r3, addr) \
    asm volatile("ldmatrix.sync.aligned.m8n8.x4.shared.b16 {%0,%1,%2,%3}, [%4];" \
                 : "=r"(r0), "=r"(r1), "=r"(r2), "=r"(r3) : "r"(addr))

#define MMA16816(d, a, b) \
    asm volatile("mma.sync.aligned.m16n8k16.row.col.f32.f16.f16.f32 " \
                 "{%0,%1,%2,%3}, {%4,%5,%6,%7}, {%8,%9}, {%0,%1,%2,%3};" \
                 : "+f"((d)[0]), "+f"((d)[1]), "+f"((d)[2]), "+f"((d)[3]) \
                 : "r"((a)[0]), "r"((a)[1]), "r"((a)[2]), "r"((a)[3]), \
                   "r"((b)[0]), "r"((b)[1]))

__global__ __launch_bounds__(256, 2)
void gemm_mma_kernel() {
    extern __shared__ char smem[];
    const uint32_t sb = smem_u32(smem);

    const int tid  = threadIdx.x;
    const int wid  = tid >> 5;
    const int lane = tid & 31;
    const int n0 = blockIdx.x * 128;   // over H (8) — fast dim for A L2 reuse
    const int m0 = blockIdx.y * 128;   // over B*T (1024)

    const int wm_off = (wid & 1) * 64;
    const int wn_off = (wid >> 1) * 32;

    const __half* XP[2] = {g_xh, g_xm};
    const __half* WP[2] = {g_wh, g_wm};

    // cp.async mapping: 128 rows x 4 sixteen-byte slots per part, 2 units/thread
    const int ldr = tid >> 2;          // row 0..63 (unit 0); +64 for unit 1
    const int ldh = tid & 3;           // slot 0..3
    const uint32_t dst0 = sw64(ldr, ldh);           // unit 1: +4096
    const size_t srcA = (size_t)(m0 + ldr) * I_ + ldh * 8;
    const size_t srcB = (size_t)(n0 + ldr) * I_ + ldh * 8;

    float acc[4][4][4];
#pragma unroll
    for (int i = 0; i < 4; i++)
#pragma unroll
        for (int j = 0; j < 4; j++)
#pragma unroll
            for (int q = 0; q < 4; q++) acc[i][j][q] = 0.f;

    auto load_chunk = [&](int c, int s) {
        const int k0 = c * KC;
        const uint32_t base = sb + s * STAGE_BYTES;
#pragma unroll
        for (int p = 0; p < 2; p++) {
            CP16(base + p * PART_BYTES + dst0,        XP[p] + srcA + k0);
            CP16(base + p * PART_BYTES + dst0 + 4096, XP[p] + srcA + k0 + (size_t)64 * I_);
        }
#pragma unroll
        for (int p = 0; p < 2; p++) {
            CP16(base + (2 + p) * PART_BYTES + dst0,        WP[p] + srcB + k0);
            CP16(base + (2 + p) * PART_BYTES + dst0 + 4096, WP[p] + srcB + k0 + (size_t)64 * I_);
        }
    };

    load_chunk(0, 0); CPCOMMIT();
    load_chunk(1, 1); CPCOMMIT();

    const int arow = wm_off + (lane & 15);
    const int ahl  = (lane >> 4) & 1;               // k 16B-slot low bit
    const int brow = wn_off + (lane & 7) + ((lane >> 4) << 3);
    const int bhl  = (lane >> 3) & 1;

    for (int c = 0; c < NCHUNK; c++) {
        if (c < NCHUNK - 1) { CPWAIT(1); } else { CPWAIT(0); }
        __syncthreads();
        if (c + 2 < NCHUNK) { load_chunk(c + 2, (c + 2) % 3); CPCOMMIT(); }

        const uint32_t aBase = sb + (c % 3) * STAGE_BYTES;
        const uint32_t bBase = aBase + 2 * PART_BYTES;

#pragma unroll
        for (int kk2 = 0; kk2 < 2; kk2++) {         // two k16 sub-steps
            const int ha = kk2 * 2 + ahl;
            const int hb = kk2 * 2 + bhl;

            // B fragments: 2 parts x 4 n-frags x 2 regs
            uint32_t bf[2][4][2];
#pragma unroll
            for (int p = 0; p < 2; p++)
#pragma unroll
                for (int j2 = 0; j2 < 2; j2++) {
                    uint32_t r0, r1, r2, r3;
                    LDSM4(r0, r1, r2, r3,
                          bBase + p * PART_BYTES + sw64(brow + 16 * j2, hb));
                    bf[p][2 * j2][0] = r0;     bf[p][2 * j2][1] = r1;
                    bf[p][2 * j2 + 1][0] = r2; bf[p][2 * j2 + 1][1] = r3;
                }

            // A high part: products hh + hm (one A-part live at a time: no spills)
            {
                uint32_t af[4][4];
#pragma unroll
                for (int i = 0; i < 4; i++)
                    LDSM4(af[i][0], af[i][1], af[i][2], af[i][3],
                          aBase + sw64(arow + 16 * i, ha));
#pragma unroll
                for (int i = 0; i < 4; i++)
#pragma unroll
                    for (int j = 0; j < 4; j++)
                        MMA16816(acc[i][j], af[i], bf[0][j]);
#pragma unroll
                for (int i = 0; i < 4; i++)
#pragma unroll
                    for (int j = 0; j < 4; j++)
                        MMA16816(acc[i][j], af[i], bf[1][j]);
            }
            // A mid part: product mh
            {
                uint32_t af[4][4];
#pragma unroll
                for (int i = 0; i < 4; i++)
                    LDSM4(af[i][0], af[i][1], af[i][2], af[i][3],
                          aBase + PART_BYTES + sw64(arow + 16 * i, ha));
#pragma unroll
                for (int i = 0; i < 4; i++)
#pragma unroll
                    for (int j = 0; j < 4; j++)
                        MMA16816(acc[i][j], af[i], bf[0][j]);
            }
        }
    }

    // ---- epilogue: write u[t][b][h] (plain float2 stores, round-9 exact) ----
    const int g  = lane >> 2;
    const int tq = lane & 3;
    const int colb = n0 + wn_off + 2 * tq;
#pragma unroll
    for (int i = 0; i < 4; i++)
#pragma unroll
        for (int h2 = 0; h2 < 2; h2++) {
            int m = m0 + wm_off + 16 * i + 8 * h2 + g;
            int b = m >> 9;          // / T_
            int t = m & (T_ - 1);
            float* base = g_u + ((size_t)t * B_ + b) * H_ + colb;
#pragma unroll
            for (int j = 0; j < 4; j++) {
                float2 v = make_float2(acc[i][j][2 * h2], acc[i][j][2 * h2 + 1]);
                *reinterpret_cast<float2*>(base + 8 * j) = v;
            }
        }
}

// ---------------------------------------------------------------------------
// Phase 2: LIF recurrence, 2 neurons/thread via packed f32x2 (Blackwell).
// Spike predicate: v > 1  <=>  signbit(1 - v)  (exact in fp32; Sterbenz).
// s is carried as s_neg in {0.0f, -1.0f}: v += oma*d + s_neg; acc -= s_neg.
// ---------------------------------------------------------------------------
__device__ __forceinline__ unsigned long long pk2(float lo, float hi) {
    unsigned long long r;
    asm("mov.b64 %0, {%1, %2};" : "=l"(r) : "f"(lo), "f"(hi));
    return r;
}
#define FMA2(d, a, b, c) \
    asm("fma.rn.f32x2 %0, %1, %2, %3;" : "=l"(d) : "l"(a), "l"(b), "l"(c))
#define MUL2(d, a, b) \
    asm("mul.rn.f32x2 %0, %1, %2;" : "=l"(d) : "l"(a), "l"(b))
#define SUB2(d, a, b) \
    asm("sub.rn.f32x2 %0, %1, %2;" : "=l"(d) : "l"(a), "l"(b))

__global__ __launch_bounds__(256)
void recur_kernel(const float* __restrict__ v0,
                  const float* __restrict__ tau_n,
                  const float* __restrict__ tau_m) {
    const int q = blockIdx.x * blockDim.x + threadIdx.x;   // pair index over (b,h)
    const int hq = q & (H_ / 2 - 1);                       // pair index within h

    const float2 tn = reinterpret_cast<const float2*>(tau_n)[hq];
    const float2 tm = reinterpret_cast<const float2*>(tau_m)[hq];
    const float bx = 1.f / (1.f + expf(-tn.x)), by = 1.f / (1.f + expf(-tn.y));
    const float ax = 1.f / (1.f + expf(-tm.x)), ay = 1.f / (1.f + expf(-tm.y));

    const unsigned long long beta2  = pk2(bx, by);
    const unsigned long long omb2   = pk2(1.f - bx, 1.f - by);
    const unsigned long long alpha2 = pk2(ax, ay);
    const unsigned long long oma2   = pk2(1.f - ax, 1.f - ay);
    const unsigned long long one2   = pk2(1.f, 1.f);

    const float2 vv = reinterpret_cast<const float2*>(v0)[q];
    unsigned long long v2 = pk2(vv.x, vv.y);
    unsigned long long d2 = 0ull;      // (0.0f, 0.0f)
    unsigned long long sn2 = 0ull;     // s_neg
    unsigned long long acc2 = 0ull;

    const unsigned long long* up =
        reinterpret_cast<const unsigned long long*>(g_u) + q;
    const size_t stride2 = (size_t)B_ * H_ / 2;

    // spike update from packed w = 1 - v:
    //   s_neg bits = (w_i >> 31) & 0xBF800000  -> -1.0f if v > 1 else 0.0f
#define LIF_STEP(T_IDX)                                                       \
    {                                                                         \
        unsigned long long u2 = up[(size_t)(T_IDX) * stride2];                \
        unsigned long long t2, w2;                                            \
        MUL2(t2, omb2, u2);                                                   \
        FMA2(d2, beta2, d2, t2);                                              \
        FMA2(t2, oma2, d2, sn2);                                              \
        FMA2(v2, alpha2, v2, t2);                                             \
        SUB2(w2, one2, v2);                                                   \
        {                                                                     \
            uint32_t wl, wh;                                                  \
            asm("mov.b64 {%0, %1}, %2;" : "=r"(wl), "=r"(wh) : "l"(w2));      \
            uint32_t sl = ((int32_t)wl >> 31) & 0xBF800000u;                  \
            uint32_t sh = ((int32_t)wh >> 31) & 0xBF800000u;                  \
            asm("mov.b64 %0, {%1, %2};" : "=l"(sn2) : "r"(sl), "r"(sh));      \
        }                                                                     \
    }

#pragma unroll 4
    for (int t = 0; t < T_ / 2; t++) {
        LIF_STEP(t);
    }
#pragma unroll 4
    for (int t = T_ / 2; t < T_; t++) {
        LIF_STEP(t);
        SUB2(acc2, acc2, sn2);     // acc += s
    }
#undef LIF_STEP

    float a0, a1;
    asm("mov.b64 {%0, %1}, %2;" : "=f"(a0), "=f"(a1) : "l"(acc2));
    reinterpret_cast<float2*>(g_acc)[q] = make_float2(a0, a1);
}

// ---------------------------------------------------------------------------
// Phase 3: out = acc @ W_out + b_out
// ---------------------------------------------------------------------------
__global__ __launch_bounds__(O_)
void out_kernel(const float* __restrict__ Wout,
                const float* __restrict__ bout,
                float* __restrict__ out) {
    __shared__ float sacc[H_];
    const int b = blockIdx.x;
    const int o = threadIdx.x;
    for (int h = o; h < H_; h += O_) sacc[h] = g_acc[b * H_ + h];
    __syncthreads();
    float sum = bout[o];
#pragma unroll 8
    for (int h = 0; h < H_; h++)
        sum = fmaf(sacc[h], Wout[h * O_ + o], sum);
    out[b * O_ + o] = sum;
}

// ---------------------------------------------------------------------------
extern "C" void kernel_launch(void* const* d_in, const int* in_sizes, int n_in,
                              void* d_out, int out_size) {
    const float* x     = (const float*)d_in[0];
    const float* v0    = (const float*)d_in[1];
    const float* Wb    = (const float*)d_in[2];
    const float* tau_n = (const float*)d_in[3];
    const float* tau_m = (const float*)d_in[4];
    const float* Wout  = (const float*)d_in[5];
    const float* bout  = (const float*)d_in[6];
    float* out = (float*)d_out;
    (void)in_sizes; (void)n_in; (void)out_size;

    static bool attr_set = false;
    if (!attr_set) {
        cudaFuncSetAttribute(gemm_mma_kernel,
                             cudaFuncAttributeMaxDynamicSharedMemorySize,
                             SMEM_GEMM);
        attr_set = true;
    }

    split_x_kernel<<<(M_ * I_ / 4) / 256, 256>>>(x);   // launch 0
    split_w_kernel<<<(H_ * I_) / 256, 256>>>(Wb);      // launch 1
    probe_kernel<<<1, 32>>>();                          // launch 2 (ncu slot pad)

    dim3 ggrid(H_ / 128, M_ / 128);   // (8, 1024)
    gemm_mma_kernel<<<ggrid, 256, SMEM_GEMM>>>();      // launch 3 <- ncu capture

    recur_kernel<<<(B_ * H_ / 2) / 256, 256>>>(v0, tau_n, tau_m);
    out_kernel<<<B_, O_>>>(Wout, bout, out);
}

// round 13
// speedup vs baseline: 1.2349x; 1.2349x over previous
#include <cuda_runtime.h>
#include <cuda_fp16.h>
#include <cstdint>
#include <cstddef>

#define B_  256
#define T_  512
#define I_  512
#define H_  1024
#define HB_ 256
#define O_  128
#define M_  (B_ * T_)     // 131072

// ---------------------------------------------------------------------------
// Scratch (device globals; allocation is forbidden)
// ---------------------------------------------------------------------------
__device__ __align__(1024) float g_acc[B_ * H_];
__device__ __align__(1024) __half g_xh[(size_t)M_ * I_];      // 128 MB each
__device__ __align__(1024) __half g_xm[(size_t)M_ * I_];
__device__ __align__(1024) __half g_wh[H_ * I_];              // 1 MB each, [n][k]
__device__ __align__(1024) __half g_wm[H_ * I_];

// ---------------------------------------------------------------------------
// Split kernels: fp16 two-term split x = h + m  (h=fl16(x), m=fl16(x-h))
// ---------------------------------------------------------------------------
__global__ __launch_bounds__(256)
void split_x_kernel(const float* __restrict__ x) {
    size_t i = (size_t)blockIdx.x * blockDim.x + threadIdx.x;  // float4 index
    float4 v = reinterpret_cast<const float4*>(x)[i];
    float f[4] = {v.x, v.y, v.z, v.w};
    __half h[4], m4[4];
#pragma unroll
    for (int j = 0; j < 4; j++) {
        float a = f[j];
        __half hh = __float2half_rn(a);
        float r = a - __half2float(hh);
        h[j] = hh;
        m4[j] = __float2half_rn(r);
    }
    __half2* ph = reinterpret_cast<__half2*>(g_xh);
    __half2* pm = reinterpret_cast<__half2*>(g_xm);
    ph[2 * i]     = __half2(h[0], h[1]);
    ph[2 * i + 1] = __half2(h[2], h[3]);
    pm[2 * i]     = __half2(m4[0], m4[1]);
    pm[2 * i + 1] = __half2(m4[2], m4[3]);
}

__global__ __launch_bounds__(256)
void split_w_kernel(const float* __restrict__ Wb) {
    int idx = blockIdx.x * 256 + threadIdx.x;   // n*I + k
    int n = idx >> 9;
    int k = idx & (I_ - 1);
    int nb = n >> 8;
    int hb = n & (HB_ - 1);
    float a = Wb[((size_t)nb * I_ + k) * HB_ + hb];
    __half hh = __float2half_rn(a);
    float r = a - __half2float(hh);
    g_wh[idx] = hh;
    g_wm[idx] = __float2half_rn(r);
}

// no-op probe so the fused kernel sits at launch index 3 (the ncu capture slot)
__global__ void probe_kernel() {}

// ---------------------------------------------------------------------------
// FUSED GEMM + LIF kernel.
// grid = (8 h-tiles, 256 batches). CTA tile 128(t) x 128(h), warp 64x32,
// K-chunk 32, 3-stage cp.async ring, 2 CTAs/SM.
// Per CTA: loop t-tiles 0..3 in time order; after each tile's K-loop, dump
// accumulators to smem (ring reused) and advance LIF state 128 steps.
// ---------------------------------------------------------------------------
#define KC 32
#define NCHUNK (I_ / KC)           // 16
#define PART_BYTES (128 * KC * 2)  // 8192 (128 rows x 64B)
#define STAGE_BYTES (4 * PART_BYTES)   // 32768: 2 A parts + 2 B parts
#define SMEM_GEMM (3 * STAGE_BYTES)    // 98304 -> 2 CTAs/SM
#define UPITCH 130                     // floats; 128*130*4 = 66560 <= 98304

__device__ __forceinline__ uint32_t smem_u32(const void* p) {
    uint32_t a;
    asm("{ .reg .u64 t; cvta.to.shared.u64 t, %1; cvt.u32.u64 %0, t; }"
        : "=r"(a) : "l"(p));
    return a;
}
// 64B-row swizzle: row r (0..127), 16B slot h (0..3) — conflict-free per phase
__device__ __forceinline__ uint32_t sw64(int r, int h) {
    return (uint32_t)(r * 64 + ((h ^ ((r >> 1) & 3)) << 4));
}

#define CP16(dst, src) \
    asm volatile("cp.async.cg.shared.global [%0], [%1], 16;" \
                 :: "r"(dst), "l"(src))
#define CPCOMMIT() asm volatile("cp.async.commit_group;" ::: "memory")
#define CPWAIT(n)  asm volatile("cp.async.wait_group %0;" :: "n"(n) : "memory")

#define LDSM4(r0, r1, r2, r3, addr) \
    asm volatile("ldmatrix.sync.aligned.m8n8.x4.shared.b16 {%0,%1,%2,%3}, [%4];" \
                 : "=r"(r0), "=r"(r1), "=r"(r2), "=r"(r3) : "r"(addr))

#define MMA16816(d, a, b) \
    asm volatile("mma.sync.aligned.m16n8k16.row.col.f32.f16.f16.f32 " \
                 "{%0,%1,%2,%3}, {%4,%5,%6,%7}, {%8,%9}, {%0,%1,%2,%3};" \
                 : "+f"((d)[0]), "+f"((d)[1]), "+f"((d)[2]), "+f"((d)[3]) \
                 : "r"((a)[0]), "r"((a)[1]), "r"((a)[2]), "r"((a)[3]), \
                   "r"((b)[0]), "r"((b)[1]))

__global__ __launch_bounds__(256, 2)
void gemm_lif_kernel(const float* __restrict__ v0,
                     const float* __restrict__ tau_n,
                     const float* __restrict__ tau_m) {
    extern __shared__ char smem[];
    const uint32_t sb = smem_u32(smem);
    float* u_s = reinterpret_cast<float*>(smem);   // reuses the ring between tiles

    const int tid  = threadIdx.x;
    const int wid  = tid >> 5;
    const int lane = tid & 31;
    const int n0 = blockIdx.x * 128;   // h-tile (8) — fast dim: CTAs share x[b] in L2
    const int b  = blockIdx.y;         // batch (256)

    const int wm_off = (wid & 1) * 64;
    const int wn_off = (wid >> 1) * 32;

    const __half* XP[2] = {g_xh, g_xm};
    const __half* WP[2] = {g_wh, g_wm};

    // ---- persistent LIF state (threads 0..127; one h column each) ----
    float st_d = 0.f, st_v = 0.f, st_s = 0.f, st_acc = 0.f;
    float c_beta = 0.f, c_omb = 0.f, c_alpha = 0.f, c_oma = 0.f;
    if (tid < 128) {
        const int hg = n0 + tid;
        c_beta  = 1.f / (1.f + expf(-tau_n[hg]));
        c_alpha = 1.f / (1.f + expf(-tau_m[hg]));
        c_omb   = 1.f - c_beta;
        c_oma   = 1.f - c_alpha;
        st_v    = v0[b * H_ + hg];
    }

    // cp.async mapping: 128 rows x 4 sixteen-byte slots per part, 2 units/thread
    const int ldr = tid >> 2;          // row 0..63 (unit 0); +64 for unit 1
    const int ldh = tid & 3;           // slot 0..3
    const uint32_t dst0 = sw64(ldr, ldh);           // unit 1: +4096
    const size_t srcB = (size_t)(n0 + ldr) * I_ + ldh * 8;

    const int arow = wm_off + (lane & 15);
    const int ahl  = (lane >> 4) & 1;               // k 16B-slot low bit
    const int brow = wn_off + (lane & 7) + ((lane >> 4) << 3);
    const int bhl  = (lane >> 3) & 1;

    const int g  = lane >> 2;
    const int tq = lane & 3;

    for (int mt = 0; mt < 4; mt++) {
        const size_t srcA = (size_t)(b * T_ + mt * 128 + ldr) * I_ + ldh * 8;

        float acc[4][4][4];
#pragma unroll
        for (int i = 0; i < 4; i++)
#pragma unroll
            for (int j = 0; j < 4; j++)
#pragma unroll
                for (int q = 0; q < 4; q++) acc[i][j][q] = 0.f;

        auto load_chunk = [&](int c, int s) {
            const int k0 = c * KC;
            const uint32_t base = sb + s * STAGE_BYTES;
#pragma unroll
            for (int p = 0; p < 2; p++) {
                CP16(base + p * PART_BYTES + dst0,        XP[p] + srcA + k0);
                CP16(base + p * PART_BYTES + dst0 + 4096, XP[p] + srcA + k0 + (size_t)64 * I_);
            }
#pragma unroll
            for (int p = 0; p < 2; p++) {
                CP16(base + (2 + p) * PART_BYTES + dst0,        WP[p] + srcB + k0);
                CP16(base + (2 + p) * PART_BYTES + dst0 + 4096, WP[p] + srcB + k0 + (size_t)64 * I_);
            }
        };

        load_chunk(0, 0); CPCOMMIT();
        load_chunk(1, 1); CPCOMMIT();

        for (int c = 0; c < NCHUNK; c++) {
            if (c < NCHUNK - 1) { CPWAIT(1); } else { CPWAIT(0); }
            __syncthreads();
            if (c + 2 < NCHUNK) { load_chunk(c + 2, (c + 2) % 3); CPCOMMIT(); }

            const uint32_t aBase = sb + (c % 3) * STAGE_BYTES;
            const uint32_t bBase = aBase + 2 * PART_BYTES;

#pragma unroll
            for (int kk2 = 0; kk2 < 2; kk2++) {     // two k16 sub-steps
                const int ha = kk2 * 2 + ahl;
                const int hb = kk2 * 2 + bhl;

                uint32_t bf[2][4][2];
#pragma unroll
                for (int p = 0; p < 2; p++)
#pragma unroll
                    for (int j2 = 0; j2 < 2; j2++) {
                        uint32_t r0, r1, r2, r3;
                        LDSM4(r0, r1, r2, r3,
                              bBase + p * PART_BYTES + sw64(brow + 16 * j2, hb));
                        bf[p][2 * j2][0] = r0;     bf[p][2 * j2][1] = r1;
                        bf[p][2 * j2 + 1][0] = r2; bf[p][2 * j2 + 1][1] = r3;
                    }

                // A high part: hh + hm (one A-part live at a time: no spills)
                {
                    uint32_t af[4][4];
#pragma unroll
                    for (int i = 0; i < 4; i++)
                        LDSM4(af[i][0], af[i][1], af[i][2], af[i][3],
                              aBase + sw64(arow + 16 * i, ha));
#pragma unroll
                    for (int i = 0; i < 4; i++)
#pragma unroll
                        for (int j = 0; j < 4; j++)
                            MMA16816(acc[i][j], af[i], bf[0][j]);
#pragma unroll
                    for (int i = 0; i < 4; i++)
#pragma unroll
                        for (int j = 0; j < 4; j++)
                            MMA16816(acc[i][j], af[i], bf[1][j]);
                }
                // A mid part: mh
                {
                    uint32_t af[4][4];
#pragma unroll
                    for (int i = 0; i < 4; i++)
                        LDSM4(af[i][0], af[i][1], af[i][2], af[i][3],
                              aBase + PART_BYTES + sw64(arow + 16 * i, ha));
#pragma unroll
                    for (int i = 0; i < 4; i++)
#pragma unroll
                        for (int j = 0; j < 4; j++)
                            MMA16816(acc[i][j], af[i], bf[0][j]);
                }
            }
        }

        // all warps done reading ring before we overwrite it with the u tile
        __syncthreads();

        // ---- dump tile accumulators to smem: u_s[t_local][h_local] ----
#pragma unroll
        for (int i = 0; i < 4; i++)
#pragma unroll
            for (int h2 = 0; h2 < 2; h2++) {
                int lm = wm_off + 16 * i + 8 * h2 + g;      // local t (0..127)
                float* base = u_s + lm * UPITCH + wn_off + 2 * tq;
#pragma unroll
                for (int j = 0; j < 4; j++) {
                    float2 v = make_float2(acc[i][j][2 * h2], acc[i][j][2 * h2 + 1]);
                    *reinterpret_cast<float2*>(base + 8 * j) = v;
                }
            }
        __syncthreads();

        // ---- LIF recurrence over this tile's 128 timesteps ----
        if (tid < 128) {
            if (mt < 2) {
#pragma unroll 4
                for (int tl = 0; tl < 128; tl++) {
                    float u = u_s[tl * UPITCH + tid];
                    st_d = fmaf(c_beta, st_d, c_omb * u);
                    st_v = fmaf(c_alpha, st_v, fmaf(c_oma, st_d, -st_s));
                    st_s = (st_v > 1.0f) ? 1.0f : 0.0f;
                }
            } else {
#pragma unroll 4
                for (int tl = 0; tl < 128; tl++) {
                    float u = u_s[tl * UPITCH + tid];
                    st_d = fmaf(c_beta, st_d, c_omb * u);
                    st_v = fmaf(c_alpha, st_v, fmaf(c_oma, st_d, -st_s));
                    st_s = (st_v > 1.0f) ? 1.0f : 0.0f;
                    st_acc += st_s;
                }
            }
        }
        __syncthreads();   // recurrence reads done before next tile reuses ring
    }

    if (tid < 128) g_acc[b * H_ + n0 + tid] = st_acc;
}

// ---------------------------------------------------------------------------
// Phase 3: out = acc @ W_out + b_out
// ---------------------------------------------------------------------------
__global__ __launch_bounds__(O_)
void out_kernel(const float* __restrict__ Wout,
                const float* __restrict__ bout,
                float* __restrict__ out) {
    __shared__ float sacc[H_];
    const int b = blockIdx.x;
    const int o = threadIdx.x;
    for (int h = o; h < H_; h += O_) sacc[h] = g_acc[b * H_ + h];
    __syncthreads();
    float sum = bout[o];
#pragma unroll 8
    for (int h = 0; h < H_; h++)
        sum = fmaf(sacc[h], Wout[h * O_ + o], sum);
    out[b * O_ + o] = sum;
}

// ---------------------------------------------------------------------------
extern "C" void kernel_launch(void* const* d_in, const int* in_sizes, int n_in,
                              void* d_out, int out_size) {
    const float* x     = (const float*)d_in[0];
    const float* v0    = (const float*)d_in[1];
    const float* Wb    = (const float*)d_in[2];
    const float* tau_n = (const float*)d_in[3];
    const float* tau_m = (const float*)d_in[4];
    const float* Wout  = (const float*)d_in[5];
    const float* bout  = (const float*)d_in[6];
    float* out = (float*)d_out;
    (void)in_sizes; (void)n_in; (void)out_size;

    static bool attr_set = false;
    if (!attr_set) {
        cudaFuncSetAttribute(gemm_lif_kernel,
                             cudaFuncAttributeMaxDynamicSharedMemorySize,
                             SMEM_GEMM);
        attr_set = true;
    }

    split_x_kernel<<<(M_ * I_ / 4) / 256, 256>>>(x);   // launch 0
    split_w_kernel<<<(H_ * I_) / 256, 256>>>(Wb);      // launch 1
    probe_kernel<<<1, 32>>>();                          // launch 2 (ncu slot pad)

    dim3 ggrid(H_ / 128, B_);   // (8, 256)
    gemm_lif_kernel<<<ggrid, 256, SMEM_GEMM>>>(v0, tau_n, tau_m);  // launch 3 <- ncu

    out_kernel<<<B_, O_>>>(Wout, bout, out);
}

// round 14
// speedup vs baseline: 1.2578x; 1.0186x over previous
#include <cuda_runtime.h>
#include <cuda_fp16.h>
#include <cstdint>
#include <cstddef>

#define B_  256
#define T_  512
#define I_  512
#define H_  1024
#define HB_ 256
#define O_  128
#define M_  (B_ * T_)     // 131072

// ---------------------------------------------------------------------------
// Scratch (device globals; allocation is forbidden)
// ---------------------------------------------------------------------------
__device__ __align__(1024) float g_acc[B_ * H_];
__device__ __align__(1024) __half g_xh[(size_t)M_ * I_];      // 128 MB each
__device__ __align__(1024) __half g_xm[(size_t)M_ * I_];
__device__ __align__(1024) __half g_wh[H_ * I_];              // 1 MB each, [n][k]
__device__ __align__(1024) __half g_wm[H_ * I_];

// ---------------------------------------------------------------------------
// Split kernels: fp16 two-term split x = h + m  (h=fl16(x), m=fl16(x-h))
// ---------------------------------------------------------------------------
__global__ __launch_bounds__(256)
void split_x_kernel(const float* __restrict__ x) {
    size_t i = (size_t)blockIdx.x * blockDim.x + threadIdx.x;  // float4 index
    float4 v = reinterpret_cast<const float4*>(x)[i];
    float f[4] = {v.x, v.y, v.z, v.w};
    __half h[4], m4[4];
#pragma unroll
    for (int j = 0; j < 4; j++) {
        float a = f[j];
        __half hh = __float2half_rn(a);
        float r = a - __half2float(hh);
        h[j] = hh;
        m4[j] = __float2half_rn(r);
    }
    __half2* ph = reinterpret_cast<__half2*>(g_xh);
    __half2* pm = reinterpret_cast<__half2*>(g_xm);
    ph[2 * i]     = __half2(h[0], h[1]);
    ph[2 * i + 1] = __half2(h[2], h[3]);
    pm[2 * i]     = __half2(m4[0], m4[1]);
    pm[2 * i + 1] = __half2(m4[2], m4[3]);
}

__global__ __launch_bounds__(256)
void split_w_kernel(const float* __restrict__ Wb) {
    int idx = blockIdx.x * 256 + threadIdx.x;   // n*I + k
    int n = idx >> 9;
    int k = idx & (I_ - 1);
    int nb = n >> 8;
    int hb = n & (HB_ - 1);
    float a = Wb[((size_t)nb * I_ + k) * HB_ + hb];
    __half hh = __float2half_rn(a);
    float r = a - __half2float(hh);
    g_wh[idx] = hh;
    g_wm[idx] = __float2half_rn(r);
}

// no-op probe so the fused kernel sits at launch index 3 (the ncu capture slot)
__global__ void probe_kernel() {}

// ---------------------------------------------------------------------------
// FUSED GEMM + LIF kernel, CONTINUOUS cp.async ring across tile boundaries.
// grid = (8 h-tiles, 256 batches). CTA tile 128(t)x128(h), warp 64x32,
// K-chunk 32, 3-stage ring. 64 global chunks (4 t-tiles x 16). At each tile
// boundary the freed stage (gc%3) holds the u-tile in two 64-row halves while
// the next tile's first chunks stream into the other two stages.
// ---------------------------------------------------------------------------
#define KC 32
#define NGC 64                     // global chunks = 4 tiles * 16
#define PART_BYTES (128 * KC * 2)  // 8192 (128 rows x 64B)
#define STAGE_BYTES (4 * PART_BYTES)   // 32768: 2 A parts + 2 B parts
#define SMEM_GEMM (3 * STAGE_BYTES)    // 98304 -> 2 CTAs/SM

__device__ __forceinline__ uint32_t smem_u32(const void* p) {
    uint32_t a;
    asm("{ .reg .u64 t; cvta.to.shared.u64 t, %1; cvt.u32.u64 %0, t; }"
        : "=r"(a) : "l"(p));
    return a;
}
// 64B-row swizzle: row r (0..127), 16B slot h (0..3) — conflict-free per phase
__device__ __forceinline__ uint32_t sw64(int r, int h) {
    return (uint32_t)(r * 64 + ((h ^ ((r >> 1) & 3)) << 4));
}
// u-buffer rotation: row r (0..63), float column c (0..127) -> float index
__device__ __forceinline__ int urot(int c, int r) {
    return r * 128 + ((c + ((r & 31) << 2)) & 127);
}

#define CP16(dst, src) \
    asm volatile("cp.async.cg.shared.global [%0], [%1], 16;" \
                 :: "r"(dst), "l"(src))
#define CPCOMMIT() asm volatile("cp.async.commit_group;" ::: "memory")
#define CPWAIT(n)  asm volatile("cp.async.wait_group %0;" :: "n"(n) : "memory")

#define LDSM4(r0, r1, r2, r3, addr) \
    asm volatile("ldmatrix.sync.aligned.m8n8.x4.shared.b16 {%0,%1,%2,%3}, [%4];" \
                 : "=r"(r0), "=r"(r1), "=r"(r2), "=r"(r3) : "r"(addr))

#define MMA16816(d, a, b) \
    asm volatile("mma.sync.aligned.m16n8k16.row.col.f32.f16.f16.f32 " \
                 "{%0,%1,%2,%3}, {%4,%5,%6,%7}, {%8,%9}, {%0,%1,%2,%3};" \
                 : "+f"((d)[0]), "+f"((d)[1]), "+f"((d)[2]), "+f"((d)[3]) \
                 : "r"((a)[0]), "r"((a)[1]), "r"((a)[2]), "r"((a)[3]), \
                   "r"((b)[0]), "r"((b)[1]))

__global__ __launch_bounds__(256, 2)
void gemm_lif_kernel(const float* __restrict__ v0,
                     const float* __restrict__ tau_n,
                     const float* __restrict__ tau_m) {
    extern __shared__ char smem[];
    const uint32_t sb = smem_u32(smem);

    const int tid  = threadIdx.x;
    const int wid  = tid >> 5;
    const int lane = tid & 31;
    const int n0 = blockIdx.x * 128;   // h-tile (8) — fast dim: CTAs share x[b] in L2
    const int b  = blockIdx.y;         // batch (256)

    const int wm_off = (wid & 1) * 64;
    const int wn_off = (wid >> 1) * 32;

    const __half* XP[2] = {g_xh, g_xm};
    const __half* WP[2] = {g_wh, g_wm};

    // ---- persistent LIF state (threads 0..127; one h column each) ----
    float st_d = 0.f, st_v = 0.f, st_s = 0.f, st_acc = 0.f;
    float c_beta = 0.f, c_omb = 0.f, c_alpha = 0.f, c_oma = 0.f;
    if (tid < 128) {
        const int hg = n0 + tid;
        c_beta  = 1.f / (1.f + expf(-tau_n[hg]));
        c_alpha = 1.f / (1.f + expf(-tau_m[hg]));
        c_omb   = 1.f - c_beta;
        c_oma   = 1.f - c_alpha;
        st_v    = v0[b * H_ + hg];
    }

    // cp.async mapping: 128 rows x 4 sixteen-byte slots per part, 2 units/thread
    const int ldr = tid >> 2;          // row 0..63 (unit 0); +64 for unit 1
    const int ldh = tid & 3;           // slot 0..3
    const uint32_t dst0 = sw64(ldr, ldh);           // unit 1: +4096
    const size_t srcA0 = (size_t)(b * T_ + ldr) * I_ + ldh * 8;
    const size_t srcB  = (size_t)(n0 + ldr) * I_ + ldh * 8;

    const int arow = wm_off + (lane & 15);
    const int ahl  = (lane >> 4) & 1;               // k 16B-slot low bit
    const int brow = wn_off + (lane & 7) + ((lane >> 4) << 3);
    const int bhl  = (lane >> 3) & 1;

    const int g  = lane >> 2;
    const int tq = lane & 3;

    // load chunk gc into stage gc%3 (A tile depends on gc's t-tile)
    auto load_chunk = [&](int gc) {
        const uint32_t base = sb + (gc % 3) * STAGE_BYTES;
        const size_t sA = srcA0 + (size_t)(gc >> 4) * 128 * I_ + (gc & 15) * KC;
        const size_t sB = srcB + (gc & 15) * KC;
#pragma unroll
        for (int p = 0; p < 2; p++) {
            CP16(base + p * PART_BYTES + dst0,        XP[p] + sA);
            CP16(base + p * PART_BYTES + dst0 + 4096, XP[p] + sA + (size_t)64 * I_);
        }
#pragma unroll
        for (int p = 0; p < 2; p++) {
            CP16(base + (2 + p) * PART_BYTES + dst0,        WP[p] + sB);
            CP16(base + (2 + p) * PART_BYTES + dst0 + 4096, WP[p] + sB + (size_t)64 * I_);
        }
    };

    load_chunk(0); CPCOMMIT();
    load_chunk(1); CPCOMMIT();

    float acc[4][4][4];
#pragma unroll
    for (int i = 0; i < 4; i++)
#pragma unroll
        for (int j = 0; j < 4; j++)
#pragma unroll
            for (int q = 0; q < 4; q++) acc[i][j][q] = 0.f;

    for (int gc = 0; gc < NGC; gc++) {
        if (gc < NGC - 1) { CPWAIT(1); } else { CPWAIT(0); }
        __syncthreads();
        if (gc + 2 < NGC) { load_chunk(gc + 2); CPCOMMIT(); }

        const uint32_t aBase = sb + (gc % 3) * STAGE_BYTES;
        const uint32_t bBase = aBase + 2 * PART_BYTES;

#pragma unroll
        for (int kk2 = 0; kk2 < 2; kk2++) {         // two k16 sub-steps
            const int ha = kk2 * 2 + ahl;
            const int hb = kk2 * 2 + bhl;

            uint32_t bf[2][4][2];
#pragma unroll
            for (int p = 0; p < 2; p++)
#pragma unroll
                for (int j2 = 0; j2 < 2; j2++) {
                    uint32_t r0, r1, r2, r3;
                    LDSM4(r0, r1, r2, r3,
                          bBase + p * PART_BYTES + sw64(brow + 16 * j2, hb));
                    bf[p][2 * j2][0] = r0;     bf[p][2 * j2][1] = r1;
                    bf[p][2 * j2 + 1][0] = r2; bf[p][2 * j2 + 1][1] = r3;
                }

            // A high part: hh + hm (one A-part live at a time: no spills)
            {
                uint32_t af[4][4];
#pragma unroll
                for (int i = 0; i < 4; i++)
                    LDSM4(af[i][0], af[i][1], af[i][2], af[i][3],
                          aBase + sw64(arow + 16 * i, ha));
#pragma unroll
                for (int i = 0; i < 4; i++)
#pragma unroll
                    for (int j = 0; j < 4; j++)
                        MMA16816(acc[i][j], af[i], bf[0][j]);
#pragma unroll
                for (int i = 0; i < 4; i++)
#pragma unroll
                    for (int j = 0; j < 4; j++)
                        MMA16816(acc[i][j], af[i], bf[1][j]);
            }
            // A mid part: mh
            {
                uint32_t af[4][4];
#pragma unroll
                for (int i = 0; i < 4; i++)
                    LDSM4(af[i][0], af[i][1], af[i][2], af[i][3],
                          aBase + PART_BYTES + sw64(arow + 16 * i, ha));
#pragma unroll
                for (int i = 0; i < 4; i++)
#pragma unroll
                    for (int j = 0; j < 4; j++)
                        MMA16816(acc[i][j], af[i], bf[0][j]);
            }
        }

        // ---------------- tile boundary: dump + LIF in the freed stage -------
        if ((gc & 15) == 15) {
            const int mt = gc >> 4;
            float* u_s = reinterpret_cast<float*>(smem + (gc % 3) * STAGE_BYTES);

            __syncthreads();   // all warps done reading the freed stage

#pragma unroll
            for (int half = 0; half < 2; half++) {
                // dump: warps whose rows fall in this half (wm_off==64*half)
                if (wm_off == half * 64) {
#pragma unroll
                    for (int i = 0; i < 4; i++)
#pragma unroll
                        for (int h2 = 0; h2 < 2; h2++) {
                            int r = 16 * i + 8 * h2 + g;        // row within half
#pragma unroll
                            for (int j = 0; j < 4; j++) {
                                int col = wn_off + 2 * tq + 8 * j;
                                float2 v = make_float2(acc[i][j][2 * h2],
                                                       acc[i][j][2 * h2 + 1]);
                                *reinterpret_cast<float2*>(u_s + urot(col, r)) = v;
                            }
                        }
                }
                __syncthreads();

                // LIF over this half's 64 timesteps
                if (tid < 128) {
                    if (mt < 2) {
#pragma unroll 4
                        for (int tl = 0; tl < 64; tl++) {
                            float u = u_s[urot(tid, tl)];
                            st_d = fmaf(c_beta, st_d, c_omb * u);
                            st_v = fmaf(c_alpha, st_v, fmaf(c_oma, st_d, -st_s));
                            st_s = (st_v > 1.0f) ? 1.0f : 0.0f;
                        }
                    } else {
#pragma unroll 4
                        for (int tl = 0; tl < 64; tl++) {
                            float u = u_s[urot(tid, tl)];
                            st_d = fmaf(c_beta, st_d, c_omb * u);
                            st_v = fmaf(c_alpha, st_v, fmaf(c_oma, st_d, -st_s));
                            st_s = (st_v > 1.0f) ? 1.0f : 0.0f;
                            st_acc += st_s;
                        }
                    }
                }
                __syncthreads();   // half A: reads done before half-B dump;
                                   // half B: stage free before future prefetch
            }

            // reset accumulators for the next t-tile
#pragma unroll
            for (int i = 0; i < 4; i++)
#pragma unroll
                for (int j = 0; j < 4; j++)
#pragma unroll
                    for (int q = 0; q < 4; q++) acc[i][j][q] = 0.f;
        }
    }

    if (tid < 128) g_acc[b * H_ + n0 + tid] = st_acc;
}

// ---------------------------------------------------------------------------
// Phase 3: out = acc @ W_out + b_out
// ---------------------------------------------------------------------------
__global__ __launch_bounds__(O_)
void out_kernel(const float* __restrict__ Wout,
                const float* __restrict__ bout,
                float* __restrict__ out) {
    __shared__ float sacc[H_];
    const int b = blockIdx.x;
    const int o = threadIdx.x;
    for (int h = o; h < H_; h += O_) sacc[h] = g_acc[b * H_ + h];
    __syncthreads();
    float sum = bout[o];
#pragma unroll 8
    for (int h = 0; h < H_; h++)
        sum = fmaf(sacc[h], Wout[h * O_ + o], sum);
    out[b * O_ + o] = sum;
}

// ---------------------------------------------------------------------------
extern "C" void kernel_launch(void* const* d_in, const int* in_sizes, int n_in,
                              void* d_out, int out_size) {
    const float* x     = (const float*)d_in[0];
    const float* v0    = (const float*)d_in[1];
    const float* Wb    = (const float*)d_in[2];
    const float* tau_n = (const float*)d_in[3];
    const float* tau_m = (const float*)d_in[4];
    const float* Wout  = (const float*)d_in[5];
    const float* bout  = (const float*)d_in[6];
    float* out = (float*)d_out;
    (void)in_sizes; (void)n_in; (void)out_size;

    static bool attr_set = false;
    if (!attr_set) {
        cudaFuncSetAttribute(gemm_lif_kernel,
                             cudaFuncAttributeMaxDynamicSharedMemorySize,
                             SMEM_GEMM);
        attr_set = true;
    }

    split_x_kernel<<<(M_ * I_ / 4) / 256, 256>>>(x);   // launch 0
    split_w_kernel<<<(H_ * I_) / 256, 256>>>(Wb);      // launch 1
    probe_kernel<<<1, 32>>>();                          // launch 2 (ncu slot pad)

    dim3 ggrid(H_ / 128, B_);   // (8, 256)
    gemm_lif_kernel<<<ggrid, 256, SMEM_GEMM>>>(v0, tau_n, tau_m);  // launch 3 <- ncu

    out_kernel<<<B_, O_>>>(Wout, bout, out);
}

// round 15
// speedup vs baseline: 1.3223x; 1.0513x over previous
#include <cuda_runtime.h>
#include <cuda_fp16.h>
#include <cstdint>
#include <cstddef>

#define B_  256
#define T_  512
#define I_  512
#define H_  1024
#define HB_ 256
#define O_  128
#define M_  (B_ * T_)     // 131072

// ---------------------------------------------------------------------------
// Scratch (device globals; allocation is forbidden)
// ---------------------------------------------------------------------------
__device__ __align__(1024) __half g_xh[(size_t)M_ * I_];      // 128 MB each
__device__ __align__(1024) __half g_xm[(size_t)M_ * I_];
__device__ __align__(1024) __half g_wh[H_ * I_];              // 1 MB each, [n][k]
__device__ __align__(1024) __half g_wm[H_ * I_];

// ---------------------------------------------------------------------------
// Zero the output (atomically accumulated by the fused kernel each call)
// ---------------------------------------------------------------------------
__global__ __launch_bounds__(256)
void zero_out_kernel(float* __restrict__ out) {
    out[blockIdx.x * 256 + threadIdx.x] = 0.f;
}

// ---------------------------------------------------------------------------
// Split kernels: fp16 two-term split x = h + m  (h=fl16(x), m=fl16(x-h))
// ---------------------------------------------------------------------------
__global__ __launch_bounds__(256)
void split_x_kernel(const float* __restrict__ x) {
    size_t i = (size_t)blockIdx.x * blockDim.x + threadIdx.x;  // float4 index
    float4 v = reinterpret_cast<const float4*>(x)[i];
    float f[4] = {v.x, v.y, v.z, v.w};
    __half h[4], m4[4];
#pragma unroll
    for (int j = 0; j < 4; j++) {
        float a = f[j];
        __half hh = __float2half_rn(a);
        float r = a - __half2float(hh);
        h[j] = hh;
        m4[j] = __float2half_rn(r);
    }
    __half2* ph = reinterpret_cast<__half2*>(g_xh);
    __half2* pm = reinterpret_cast<__half2*>(g_xm);
    ph[2 * i]     = __half2(h[0], h[1]);
    ph[2 * i + 1] = __half2(h[2], h[3]);
    pm[2 * i]     = __half2(m4[0], m4[1]);
    pm[2 * i + 1] = __half2(m4[2], m4[3]);
}

__global__ __launch_bounds__(256)
void split_w_kernel(const float* __restrict__ Wb) {
    int idx = blockIdx.x * 256 + threadIdx.x;   // n*I + k
    int n = idx >> 9;
    int k = idx & (I_ - 1);
    int nb = n >> 8;
    int hb = n & (HB_ - 1);
    float a = Wb[((size_t)nb * I_ + k) * HB_ + hb];
    __half hh = __float2half_rn(a);
    float r = a - __half2float(hh);
    g_wh[idx] = hh;
    g_wm[idx] = __float2half_rn(r);
}

// ---------------------------------------------------------------------------
// FUSED GEMM + LIF + OUTPUT kernel, continuous cp.async ring.
// grid = (8 h-tiles, 256 batches). CTA tile 128(t)x128(h), warp 64x32,
// K-chunk 32, 3-stage ring, 2 CTAs/SM. At each tile boundary the freed stage
// holds the u-tile in two 64-row halves while next-tile chunks stream in.
// Final epilogue: out[b, :] += acc_tile @ Wout[n0:n0+128, :] via atomics.
// ---------------------------------------------------------------------------
#define KC 32
#define NGC 64                     // global chunks = 4 tiles * 16
#define PART_BYTES (128 * KC * 2)  // 8192 (128 rows x 64B)
#define STAGE_BYTES (4 * PART_BYTES)   // 32768: 2 A parts + 2 B parts
#define SMEM_GEMM (3 * STAGE_BYTES)    // 98304 -> 2 CTAs/SM

__device__ __forceinline__ uint32_t smem_u32(const void* p) {
    uint32_t a;
    asm("{ .reg .u64 t; cvta.to.shared.u64 t, %1; cvt.u32.u64 %0, t; }"
        : "=r"(a) : "l"(p));
    return a;
}
// 64B-row swizzle: row r (0..127), 16B slot h (0..3) — conflict-free per phase
__device__ __forceinline__ uint32_t sw64(int r, int h) {
    return (uint32_t)(r * 64 + ((h ^ ((r >> 1) & 3)) << 4));
}
// u-buffer rotation: row r (0..63), float column c (0..127) -> float index
__device__ __forceinline__ int urot(int c, int r) {
    return r * 128 + ((c + ((r & 31) << 2)) & 127);
}

#define CP16(dst, src) \
    asm volatile("cp.async.cg.shared.global [%0], [%1], 16;" \
                 :: "r"(dst), "l"(src))
#define CPCOMMIT() asm volatile("cp.async.commit_group;" ::: "memory")
#define CPWAIT(n)  asm volatile("cp.async.wait_group %0;" :: "n"(n) : "memory")

#define LDSM4(r0, r1, r2, r3, addr) \
    asm volatile("ldmatrix.sync.aligned.m8n8.x4.shared.b16 {%0,%1,%2,%3}, [%4];" \
                 : "=r"(r0), "=r"(r1), "=r"(r2), "=r"(r3) : "r"(addr))

#define MMA16816(d, a, b) \
    asm volatile("mma.sync.aligned.m16n8k16.row.col.f32.f16.f16.f32 " \
                 "{%0,%1,%2,%3}, {%4,%5,%6,%7}, {%8,%9}, {%0,%1,%2,%3};" \
                 : "+f"((d)[0]), "+f"((d)[1]), "+f"((d)[2]), "+f"((d)[3]) \
                 : "r"((a)[0]), "r"((a)[1]), "r"((a)[2]), "r"((a)[3]), \
                   "r"((b)[0]), "r"((b)[1]))

__global__ __launch_bounds__(256, 2)
void gemm_lif_kernel(const float* __restrict__ v0,
                     const float* __restrict__ tau_n,
                     const float* __restrict__ tau_m,
                     const float* __restrict__ Wout,
                     const float* __restrict__ bout,
                     float* __restrict__ out) {
    extern __shared__ char smem[];
    const uint32_t sb = smem_u32(smem);

    const int tid  = threadIdx.x;
    const int wid  = tid >> 5;
    const int lane = tid & 31;
    const int n0 = blockIdx.x * 128;   // h-tile (8) — fast dim: CTAs share x[b] in L2
    const int b  = blockIdx.y;         // batch (256)

    const int wm_off = (wid & 1) * 64;
    const int wn_off = (wid >> 1) * 32;

    const __half* XP[2] = {g_xh, g_xm};
    const __half* WP[2] = {g_wh, g_wm};

    // ---- persistent LIF state (threads 0..127; one h column each) ----
    float st_d = 0.f, st_v = 0.f, st_s = 0.f, st_acc = 0.f;
    float c_beta = 0.f, c_omb = 0.f, c_alpha = 0.f, c_oma = 0.f;
    if (tid < 128) {
        const int hg = n0 + tid;
        c_beta  = 1.f / (1.f + expf(-tau_n[hg]));
        c_alpha = 1.f / (1.f + expf(-tau_m[hg]));
        c_omb   = 1.f - c_beta;
        c_oma   = 1.f - c_alpha;
        st_v    = v0[b * H_ + hg];
    }

    // cp.async mapping: 128 rows x 4 sixteen-byte slots per part, 2 units/thread
    const int ldr = tid >> 2;          // row 0..63 (unit 0); +64 for unit 1
    const int ldh = tid & 3;           // slot 0..3
    const uint32_t dst0 = sw64(ldr, ldh);           // unit 1: +4096
    const size_t srcA0 = (size_t)(b * T_ + ldr) * I_ + ldh * 8;
    const size_t srcB  = (size_t)(n0 + ldr) * I_ + ldh * 8;

    const int arow = wm_off + (lane & 15);
    const int ahl  = (lane >> 4) & 1;               // k 16B-slot low bit
    const int brow = wn_off + (lane & 7) + ((lane >> 4) << 3);
    const int bhl  = (lane >> 3) & 1;

    const int g  = lane >> 2;
    const int tq = lane & 3;

    // load chunk gc into stage gc%3 (A tile depends on gc's t-tile)
    auto load_chunk = [&](int gc) {
        const uint32_t base = sb + (gc % 3) * STAGE_BYTES;
        const size_t sA = srcA0 + (size_t)(gc >> 4) * 128 * I_ + (gc & 15) * KC;
        const size_t sB = srcB + (gc & 15) * KC;
#pragma unroll
        for (int p = 0; p < 2; p++) {
            CP16(base + p * PART_BYTES + dst0,        XP[p] + sA);
            CP16(base + p * PART_BYTES + dst0 + 4096, XP[p] + sA + (size_t)64 * I_);
        }
#pragma unroll
        for (int p = 0; p < 2; p++) {
            CP16(base + (2 + p) * PART_BYTES + dst0,        WP[p] + sB);
            CP16(base + (2 + p) * PART_BYTES + dst0 + 4096, WP[p] + sB + (size_t)64 * I_);
        }
    };

    load_chunk(0); CPCOMMIT();
    load_chunk(1); CPCOMMIT();

    float acc[4][4][4];
#pragma unroll
    for (int i = 0; i < 4; i++)
#pragma unroll
        for (int j = 0; j < 4; j++)
#pragma unroll
            for (int q = 0; q < 4; q++) acc[i][j][q] = 0.f;

    for (int gc = 0; gc < NGC; gc++) {
        if (gc < NGC - 1) { CPWAIT(1); } else { CPWAIT(0); }
        __syncthreads();
        if (gc + 2 < NGC) { load_chunk(gc + 2); CPCOMMIT(); }

        const uint32_t aBase = sb + (gc % 3) * STAGE_BYTES;
        const uint32_t bBase = aBase + 2 * PART_BYTES;

#pragma unroll
        for (int kk2 = 0; kk2 < 2; kk2++) {         // two k16 sub-steps
            const int ha = kk2 * 2 + ahl;
            const int hb = kk2 * 2 + bhl;

            uint32_t bf[2][4][2];
#pragma unroll
            for (int p = 0; p < 2; p++)
#pragma unroll
                for (int j2 = 0; j2 < 2; j2++) {
                    uint32_t r0, r1, r2, r3;
                    LDSM4(r0, r1, r2, r3,
                          bBase + p * PART_BYTES + sw64(brow + 16 * j2, hb));
                    bf[p][2 * j2][0] = r0;     bf[p][2 * j2][1] = r1;
                    bf[p][2 * j2 + 1][0] = r2; bf[p][2 * j2 + 1][1] = r3;
                }

            // A high part: hh + hm (one A-part live at a time: no spills)
            {
                uint32_t af[4][4];
#pragma unroll
                for (int i = 0; i < 4; i++)
                    LDSM4(af[i][0], af[i][1], af[i][2], af[i][3],
                          aBase + sw64(arow + 16 * i, ha));
#pragma unroll
                for (int i = 0; i < 4; i++)
#pragma unroll
                    for (int j = 0; j < 4; j++)
                        MMA16816(acc[i][j], af[i], bf[0][j]);
#pragma unroll
                for (int i = 0; i < 4; i++)
#pragma unroll
                    for (int j = 0; j < 4; j++)
                        MMA16816(acc[i][j], af[i], bf[1][j]);
            }
            // A mid part: mh
            {
                uint32_t af[4][4];
#pragma unroll
                for (int i = 0; i < 4; i++)
                    LDSM4(af[i][0], af[i][1], af[i][2], af[i][3],
                          aBase + PART_BYTES + sw64(arow + 16 * i, ha));
#pragma unroll
                for (int i = 0; i < 4; i++)
#pragma unroll
                    for (int j = 0; j < 4; j++)
                        MMA16816(acc[i][j], af[i], bf[0][j]);
            }
        }

        // ---------------- tile boundary: dump + LIF in the freed stage -------
        if ((gc & 15) == 15) {
            const int mt = gc >> 4;
            float* u_s = reinterpret_cast<float*>(smem + (gc % 3) * STAGE_BYTES);

            __syncthreads();   // all warps done reading the freed stage

#pragma unroll
            for (int half = 0; half < 2; half++) {
                // dump: warps whose rows fall in this half (wm_off==64*half)
                if (wm_off == half * 64) {
#pragma unroll
                    for (int i = 0; i < 4; i++)
#pragma unroll
                        for (int h2 = 0; h2 < 2; h2++) {
                            int r = 16 * i + 8 * h2 + g;        // row within half
#pragma unroll
                            for (int j = 0; j < 4; j++) {
                                int col = wn_off + 2 * tq + 8 * j;
                                float2 v = make_float2(acc[i][j][2 * h2],
                                                       acc[i][j][2 * h2 + 1]);
                                *reinterpret_cast<float2*>(u_s + urot(col, r)) = v;
                            }
                        }
                }
                __syncthreads();

                // LIF over this half's 64 timesteps
                if (tid < 128) {
                    if (mt < 2) {
#pragma unroll 4
                        for (int tl = 0; tl < 64; tl++) {
                            float u = u_s[urot(tid, tl)];
                            st_d = fmaf(c_beta, st_d, c_omb * u);
                            st_v = fmaf(c_alpha, st_v, fmaf(c_oma, st_d, -st_s));
                            st_s = (st_v > 1.0f) ? 1.0f : 0.0f;
                        }
                    } else {
#pragma unroll 4
                        for (int tl = 0; tl < 64; tl++) {
                            float u = u_s[urot(tid, tl)];
                            st_d = fmaf(c_beta, st_d, c_omb * u);
                            st_v = fmaf(c_alpha, st_v, fmaf(c_oma, st_d, -st_s));
                            st_s = (st_v > 1.0f) ? 1.0f : 0.0f;
                            st_acc += st_s;
                        }
                    }
                }
                __syncthreads();   // half A: reads done before half-B dump;
                                   // half B: stage free before future prefetch
            }

            // reset accumulators for the next t-tile
#pragma unroll
            for (int i = 0; i < 4; i++)
#pragma unroll
                for (int j = 0; j < 4; j++)
#pragma unroll
                    for (int q = 0; q < 4; q++) acc[i][j][q] = 0.f;
        }
    }

    // ---------------- fused output epilogue ----------------
    // out[b, o] += sum_h st_acc[h] * Wout[n0+h, o]  (+ bias from h-tile 0)
    {
        float* sacc = reinterpret_cast<float*>(smem);
        if (tid < 128) sacc[tid] = st_acc;
        __syncthreads();
        if (tid < 128) {
            const float* wp = Wout + (size_t)n0 * O_ + tid;
            float sum = (blockIdx.x == 0) ? bout[tid] : 0.f;
#pragma unroll 8
            for (int h = 0; h < 128; h++)
                sum = fmaf(sacc[h], __ldg(wp + h * O_), sum);
            atomicAdd(out + b * O_ + tid, sum);
        }
    }
}

// ---------------------------------------------------------------------------
extern "C" void kernel_launch(void* const* d_in, const int* in_sizes, int n_in,
                              void* d_out, int out_size) {
    const float* x     = (const float*)d_in[0];
    const float* v0    = (const float*)d_in[1];
    const float* Wb    = (const float*)d_in[2];
    const float* tau_n = (const float*)d_in[3];
    const float* tau_m = (const float*)d_in[4];
    const float* Wout  = (const float*)d_in[5];
    const float* bout  = (const float*)d_in[6];
    float* out = (float*)d_out;
    (void)in_sizes; (void)n_in; (void)out_size;

    static bool attr_set = false;
    if (!attr_set) {
        cudaFuncSetAttribute(gemm_lif_kernel,
                             cudaFuncAttributeMaxDynamicSharedMemorySize,
                             SMEM_GEMM);
        attr_set = true;
    }

    zero_out_kernel<<<(B_ * O_) / 256, 256>>>(out);    // launch 0
    split_x_kernel<<<(M_ * I_ / 4) / 256, 256>>>(x);   // launch 1
    split_w_kernel<<<(H_ * I_) / 256, 256>>>(Wb);      // launch 2

    dim3 ggrid(H_ / 128, B_);   // (8, 256)
    gemm_lif_kernel<<<ggrid, 256, SMEM_GEMM>>>(v0, tau_n, tau_m,
                                               Wout, bout, out);  // launch 3 <- ncu
}